// round 1
// baseline (speedup 1.0000x reference)
#include <cuda_runtime.h>
#include <cstdint>

// Problem constants: B=C=P=D=256
#define N256 256
#define EPS 1e-5f

// ---------------- scratch (device globals; no allocations allowed) ----------
__device__ float g_xemb[256 * 256 * 256];   // [B,C,D] LN'd embedding, tf32-rounded
__device__ float g_mask[256 * 256];         // [P,C] softmax mask, tf32-rounded
__device__ float g_xprompt[256 * 256];      // [P,D]
__device__ float g_xcol[256 * 256];         // [C,D] LN(emb_column)
__device__ float g_xpin[256 * 512];         // [P,2D] concat(LN(emb_prompt), prev)

// ---------------- helpers ----------------------------------------------------
__device__ __forceinline__ float to_tf32(float x) {
    uint32_t u;
    asm("cvt.rna.tf32.f32 %0, %1;" : "=r"(u) : "f"(x));
    return __uint_as_float(u);
}

__device__ __forceinline__ float block_sum256(float v, float* s) {
    int t = threadIdx.x;
    s[t] = v; __syncthreads();
    for (int off = 128; off > 0; off >>= 1) {
        if (t < off) s[t] += s[t + off];
        __syncthreads();
    }
    float r = s[0]; __syncthreads();
    return r;
}

__device__ __forceinline__ float block_max256(float v, float* s) {
    int t = threadIdx.x;
    s[t] = v; __syncthreads();
    for (int off = 128; off > 0; off >>= 1) {
        if (t < off) s[t] = fmaxf(s[t], s[t + off]);
        __syncthreads();
    }
    float r = s[0]; __syncthreads();
    return r;
}

// ---------------- K1: xp_in = [ LN(emb_prompt) | prev_cell_out ] ------------
__global__ void build_xpin_kernel(const float* __restrict__ embp,
                                  const float* __restrict__ lnpw,
                                  const float* __restrict__ lnpb,
                                  const float* __restrict__ prev) {
    __shared__ float s[256];
    int p = blockIdx.x, d = threadIdx.x;
    float v = embp[p * N256 + d];
    float mu = block_sum256(v, s) * (1.0f / 256.0f);
    float var = block_sum256(v * v, s) * (1.0f / 256.0f) - mu * mu;
    float rstd = rsqrtf(var + EPS);
    g_xpin[p * 512 + d] = (v - mu) * rstd * lnpw[d] + lnpb[d];
    g_xpin[p * 512 + 256 + d] = prev[p * N256 + d];
}

// ---------------- K2: x_col = LN(emb_column) --------------------------------
__global__ void ln_col_kernel(const float* __restrict__ embc,
                              const float* __restrict__ lncw,
                              const float* __restrict__ lncb) {
    __shared__ float s[256];
    int c = blockIdx.x, d = threadIdx.x;
    float v = embc[c * N256 + d];
    float mu = block_sum256(v, s) * (1.0f / 256.0f);
    float var = block_sum256(v * v, s) * (1.0f / 256.0f) - mu * mu;
    float rstd = rsqrtf(var + EPS);
    g_xcol[c * N256 + d] = (v - mu) * rstd * lncw[d] + lncb[d];
}

// ---------------- K3: x_prompt = xp_in @ W^T + b + emb_prompt ---------------
// M=256(p) x N=256(d) x K=512.  W is [256 out, 512 in] row-major.
__global__ void xprompt_kernel(const float* __restrict__ W,
                               const float* __restrict__ bias,
                               const float* __restrict__ embp) {
    __shared__ float As[16][17];
    __shared__ float Ws[16][17];
    int tx = threadIdx.x, ty = threadIdx.y;
    int row = blockIdx.y * 16 + ty;   // p
    int col = blockIdx.x * 16 + tx;   // d
    float acc = 0.0f;
    for (int kt = 0; kt < 32; kt++) {
        int k0 = kt * 16;
        As[ty][tx] = g_xpin[row * 512 + k0 + tx];
        Ws[ty][tx] = W[(blockIdx.x * 16 + ty) * 512 + k0 + tx];
        __syncthreads();
#pragma unroll
        for (int kk = 0; kk < 16; kk++) acc += As[ty][kk] * Ws[tx][kk];
        __syncthreads();
    }
    g_xprompt[row * N256 + col] = acc + bias[col] + embp[row * N256 + col];
}

// ---------------- K4: mask = softmax(x_prompt @ x_col^T) --------------------
__global__ void logits_softmax_kernel() {
    __shared__ float xp[256];
    __shared__ float s[256];
    int p = blockIdx.x, c = threadIdx.x;
    xp[c] = g_xprompt[p * N256 + c];
    __syncthreads();
    const float* col = g_xcol + c * N256;
    float dot = 0.0f;
#pragma unroll 8
    for (int d = 0; d < N256; d++) dot += xp[d] * col[d];
    float mx = block_max256(dot, s);
    float e = expf(dot - mx);
    float sum = block_sum256(e, s);
    g_mask[p * N256 + c] = to_tf32(e / sum);
}

// ---------------- K5: x_emb = LN(relu(bias + x*w)), tf32-rounded ------------
// one warp per (b,c) row; 8 warps per block
__global__ void xemb_kernel(const float* __restrict__ x,
                            const float* __restrict__ few,
                            const float* __restrict__ feb,
                            const float* __restrict__ lnew,
                            const float* __restrict__ lneb) {
    int lane = threadIdx.x & 31;
    int wid = threadIdx.x >> 5;
    int row = blockIdx.x * 8 + wid;            // = b*256 + c
    int c = row & 255;
    const float xv = x[row];
    const float* wrow = few + c * N256;
    const float* brow = feb + c * N256;
    float v[8];
    float sum = 0.0f, sq = 0.0f;
#pragma unroll
    for (int i = 0; i < 8; i++) {
        int d = lane + i * 32;
        float t = fmaf(xv, wrow[d], brow[d]);
        t = t > 0.0f ? t : 0.0f;
        v[i] = t;
        sum += t;
        sq = fmaf(t, t, sq);
    }
#pragma unroll
    for (int off = 16; off > 0; off >>= 1) {
        sum += __shfl_xor_sync(0xffffffff, sum, off);
        sq  += __shfl_xor_sync(0xffffffff, sq, off);
    }
    float mu = sum * (1.0f / 256.0f);
    float var = sq * (1.0f / 256.0f) - mu * mu;
    float rstd = rsqrtf(var + EPS);
    float* orow = g_xemb + row * N256;
#pragma unroll
    for (int i = 0; i < 8; i++) {
        int d = lane + i * 32;
        orow[d] = to_tf32((v[i] - mu) * rstd * lnew[d] + lneb[d]);
    }
}

// ---------------- K6: out[b] = mask @ xemb[b], tf32 mma ---------------------
// out[0,b,p,d] = (1+ew[p]) * sum_c mask[p,c]*xemb[b,c,d] + mask[b,p]*eb[b]
// Block tile 128x128, K-chunk 32, 8 warps (2x4), warp tile 64x32.
__device__ __forceinline__ void mma_tf32(float c[4],
                                         uint32_t a0, uint32_t a1, uint32_t a2, uint32_t a3,
                                         uint32_t b0, uint32_t b1) {
    asm volatile(
        "mma.sync.aligned.m16n8k8.row.col.f32.tf32.tf32.f32 "
        "{%0,%1,%2,%3}, {%4,%5,%6,%7}, {%8,%9}, {%0,%1,%2,%3};"
        : "+f"(c[0]), "+f"(c[1]), "+f"(c[2]), "+f"(c[3])
        : "r"(a0), "r"(a1), "r"(a2), "r"(a3), "r"(b0), "r"(b1));
}

__global__ __launch_bounds__(256, 2) void out_gemm_kernel(
    const float* __restrict__ ew,
    const float* __restrict__ eb,
    float* __restrict__ out) {
    __shared__ __align__(16) float As[128 * 36];   // [m][k], pad 36
    __shared__ __align__(16) float Bs[32 * 132];   // [k][n], pad 132

    int b = blockIdx.z;
    int m0 = blockIdx.y * 128;
    int n0 = blockIdx.x * 128;
    const float* A = g_mask;                 // [P=256, C=256]
    const float* B = g_xemb + b * 65536;     // [C=256, D=256]

    int tid = threadIdx.x;
    int lane = tid & 31;
    int warp = tid >> 5;
    int wm = (warp & 1) * 64;
    int wn = (warp >> 1) * 32;
    int grp = lane >> 2;      // 0..7
    int tig = lane & 3;       // 0..3

    float acc[4][4][4];
#pragma unroll
    for (int i = 0; i < 4; i++)
#pragma unroll
        for (int j = 0; j < 4; j++)
#pragma unroll
            for (int k = 0; k < 4; k++) acc[i][j][k] = 0.0f;

    for (int kt = 0; kt < 8; kt++) {
        int k0 = kt * 32;
        // A tile: 128 rows x 32 k  (1024 float4)
#pragma unroll
        for (int t = 0; t < 4; t++) {
            int idx = t * 256 + tid;
            int r = idx >> 3;
            int kc = (idx & 7) << 2;
            float4 va = *(const float4*)(A + (m0 + r) * 256 + k0 + kc);
            *(float4*)(As + r * 36 + kc) = va;
        }
        // B tile: 32 k x 128 n (1024 float4)
#pragma unroll
        for (int t = 0; t < 4; t++) {
            int idx = t * 256 + tid;
            int r = idx >> 5;
            int nc = (idx & 31) << 2;
            float4 vb = *(const float4*)(B + (k0 + r) * 256 + n0 + nc);
            *(float4*)(Bs + r * 132 + nc) = vb;
        }
        __syncthreads();

#pragma unroll
        for (int ks = 0; ks < 4; ks++) {
            int kk = ks * 8;
            uint32_t afr[4][4];
#pragma unroll
            for (int mi = 0; mi < 4; mi++) {
                int rb = wm + mi * 16 + grp;
                int cb = kk + tig;
                afr[mi][0] = __float_as_uint(As[rb * 36 + cb]);
                afr[mi][1] = __float_as_uint(As[(rb + 8) * 36 + cb]);
                afr[mi][2] = __float_as_uint(As[rb * 36 + cb + 4]);
                afr[mi][3] = __float_as_uint(As[(rb + 8) * 36 + cb + 4]);
            }
            uint32_t bfr[4][2];
#pragma unroll
            for (int ni = 0; ni < 4; ni++) {
                int nb = wn + ni * 8 + grp;
                int kb = kk + tig;
                bfr[ni][0] = __float_as_uint(Bs[kb * 132 + nb]);
                bfr[ni][1] = __float_as_uint(Bs[(kb + 4) * 132 + nb]);
            }
#pragma unroll
            for (int mi = 0; mi < 4; mi++)
#pragma unroll
                for (int ni = 0; ni < 4; ni++)
                    mma_tf32(acc[mi][ni],
                             afr[mi][0], afr[mi][1], afr[mi][2], afr[mi][3],
                             bfr[ni][0], bfr[ni][1]);
        }
        __syncthreads();
    }

    // epilogue: scale by (1+ew[p]) and add mask[b,p]*eb[b]
    const float* maskb = g_mask + b * 256;  // row b of mask
    float ebb = eb[b];
#pragma unroll
    for (int mi = 0; mi < 4; mi++) {
#pragma unroll
        for (int h = 0; h < 2; h++) {
            int p = m0 + wm + mi * 16 + grp + h * 8;
            float scale = 1.0f + ew[p];
            float addv = maskb[p] * ebb;
            long rowoff = ((long)(b * 256 + p)) * 256;
#pragma unroll
            for (int ni = 0; ni < 4; ni++) {
                int d = n0 + wn + ni * 8 + tig * 2;
                float v0 = acc[mi][ni][h * 2 + 0] * scale + addv;
                float v1 = acc[mi][ni][h * 2 + 1] * scale + addv;
                *(float2*)(out + rowoff + d) = make_float2(v0, v1);
            }
        }
    }
}

// ---------------- launch -----------------------------------------------------
extern "C" void kernel_launch(void* const* d_in, const int* in_sizes, int n_in,
                              void* d_out, int out_size) {
    const float* x    = (const float*)d_in[0];   // [B,C]
    const float* prev = (const float*)d_in[1];   // [P,D]
    const float* few  = (const float*)d_in[2];   // [C,D]
    const float* feb  = (const float*)d_in[3];   // [1,C,D]
    const float* lnew = (const float*)d_in[4];
    const float* lneb = (const float*)d_in[5];
    const float* lncw = (const float*)d_in[6];
    const float* lncb = (const float*)d_in[7];
    const float* lnpw = (const float*)d_in[8];
    const float* lnpb = (const float*)d_in[9];
    const float* diw  = (const float*)d_in[10];  // [D,2D]
    const float* dib  = (const float*)d_in[11];  // [D]
    const float* embc = (const float*)d_in[12];  // [C,D]
    const float* embp = (const float*)d_in[13];  // [P,D]
    const float* ew   = (const float*)d_in[14];  // [P,1]
    const float* ebia = (const float*)d_in[15];  // [P]
    float* out = (float*)d_out;

    build_xpin_kernel<<<256, 256>>>(embp, lnpw, lnpb, prev);
    ln_col_kernel<<<256, 256>>>(embc, lncw, lncb);
    xprompt_kernel<<<dim3(16, 16), dim3(16, 16)>>>(diw, dib, embp);
    logits_softmax_kernel<<<256, 256>>>();
    xemb_kernel<<<8192, 256>>>(x, few, feb, lnew, lneb);
    out_gemm_kernel<<<dim3(2, 2, 256), 256>>>(ew, ebia, out);
}

// round 2
// speedup vs baseline: 1.5280x; 1.5280x over previous
#include <cuda_runtime.h>
#include <cstdint>

// Problem constants: B=C=P=D=256
#define N256 256
#define EPS 1e-5f

// ---------------- scratch (device globals; no allocations allowed) ----------
__device__ float g_xemb[256 * 256 * 256];   // [B,C,D] LN'd embedding, tf32-rounded
__device__ float g_mask[256 * 256];         // [P,C] softmax mask, tf32-rounded
__device__ float g_xprompt[256 * 256];      // [P,D]
__device__ float g_xcol[256 * 256];         // [C,D] LN(emb_column)
__device__ float g_xpin[256 * 512];         // [P,2D] concat(LN(emb_prompt), prev)
__device__ float g_logits[256 * 256];       // [P,C]

// ---------------- helpers ----------------------------------------------------
__device__ __forceinline__ float to_tf32(float x) {
    uint32_t u;
    asm("cvt.rna.tf32.f32 %0, %1;" : "=r"(u) : "f"(x));
    return __uint_as_float(u);
}

__device__ __forceinline__ float block_sum256(float v, float* s) {
    int t = threadIdx.x;
    s[t] = v; __syncthreads();
    for (int off = 128; off > 0; off >>= 1) {
        if (t < off) s[t] += s[t + off];
        __syncthreads();
    }
    float r = s[0]; __syncthreads();
    return r;
}

__device__ __forceinline__ float block_max256(float v, float* s) {
    int t = threadIdx.x;
    s[t] = v; __syncthreads();
    for (int off = 128; off > 0; off >>= 1) {
        if (t < off) s[t] = fmaxf(s[t], s[t + off]);
        __syncthreads();
    }
    float r = s[0]; __syncthreads();
    return r;
}

__device__ __forceinline__ void cp_async16(void* smem, const void* gmem) {
    uint32_t s = (uint32_t)__cvta_generic_to_shared(smem);
    asm volatile("cp.async.cg.shared.global [%0], [%1], 16;\n" :: "r"(s), "l"(gmem));
}
__device__ __forceinline__ void cp_commit() {
    asm volatile("cp.async.commit_group;\n" ::: "memory");
}
template <int N>
__device__ __forceinline__ void cp_wait() {
    asm volatile("cp.async.wait_group %0;\n" :: "n"(N) : "memory");
}

// ---------------- K1: xp_in = [ LN(emb_prompt) | prev_cell_out ] ------------
__global__ void build_xpin_kernel(const float* __restrict__ embp,
                                  const float* __restrict__ lnpw,
                                  const float* __restrict__ lnpb,
                                  const float* __restrict__ prev) {
    __shared__ float s[256];
    int p = blockIdx.x, d = threadIdx.x;
    float v = embp[p * N256 + d];
    float mu = block_sum256(v, s) * (1.0f / 256.0f);
    float var = block_sum256(v * v, s) * (1.0f / 256.0f) - mu * mu;
    float rstd = rsqrtf(var + EPS);
    g_xpin[p * 512 + d] = (v - mu) * rstd * lnpw[d] + lnpb[d];
    g_xpin[p * 512 + 256 + d] = prev[p * N256 + d];
}

// ---------------- K2: x_col = LN(emb_column) --------------------------------
__global__ void ln_col_kernel(const float* __restrict__ embc,
                              const float* __restrict__ lncw,
                              const float* __restrict__ lncb) {
    __shared__ float s[256];
    int c = blockIdx.x, d = threadIdx.x;
    float v = embc[c * N256 + d];
    float mu = block_sum256(v, s) * (1.0f / 256.0f);
    float var = block_sum256(v * v, s) * (1.0f / 256.0f) - mu * mu;
    float rstd = rsqrtf(var + EPS);
    g_xcol[c * N256 + d] = (v - mu) * rstd * lncw[d] + lncb[d];
}

// ---------------- K3: x_prompt = xp_in @ W^T + b + emb_prompt ---------------
// M=256(p) x N=256(d) x K=512.  W is [256 out, 512 in] row-major.
__global__ void xprompt_kernel(const float* __restrict__ W,
                               const float* __restrict__ bias,
                               const float* __restrict__ embp) {
    __shared__ float As[16][17];
    __shared__ float Ws[16][17];
    int tx = threadIdx.x, ty = threadIdx.y;
    int row = blockIdx.y * 16 + ty;   // p
    int col = blockIdx.x * 16 + tx;   // d
    float acc = 0.0f;
    for (int kt = 0; kt < 32; kt++) {
        int k0 = kt * 16;
        As[ty][tx] = g_xpin[row * 512 + k0 + tx];
        Ws[ty][tx] = W[(blockIdx.x * 16 + ty) * 512 + k0 + tx];
        __syncthreads();
#pragma unroll
        for (int kk = 0; kk < 16; kk++) acc += As[ty][kk] * Ws[tx][kk];
        __syncthreads();
    }
    g_xprompt[row * N256 + col] = acc + bias[col] + embp[row * N256 + col];
}

// ---------------- K4a: logits = x_prompt @ x_col^T (tiled fp32 GEMM) --------
// logits[p,c] = sum_d xprompt[p,d] * xcol[c,d]
__global__ void logits_kernel() {
    __shared__ float As[16][17];
    __shared__ float Bs[16][17];   // Bs[d'][c'] (transposed on store)
    int tx = threadIdx.x, ty = threadIdx.y;
    int p = blockIdx.y * 16 + ty;
    int c = blockIdx.x * 16 + tx;
    float acc = 0.0f;
    for (int kt = 0; kt < 16; kt++) {
        int k0 = kt * 16;
        As[ty][tx] = g_xprompt[p * N256 + k0 + tx];
        Bs[tx][ty] = g_xcol[(blockIdx.x * 16 + ty) * N256 + k0 + tx];
        __syncthreads();
#pragma unroll
        for (int kk = 0; kk < 16; kk++) acc += As[ty][kk] * Bs[kk][tx];
        __syncthreads();
    }
    g_logits[p * N256 + c] = acc;
}

// ---------------- K4b: row softmax (coalesced) -------------------------------
__global__ void softmax_kernel() {
    __shared__ float s[256];
    int p = blockIdx.x, c = threadIdx.x;
    float v = g_logits[p * N256 + c];
    float mx = block_max256(v, s);
    float e = expf(v - mx);
    float sum = block_sum256(e, s);
    g_mask[p * N256 + c] = to_tf32(e / sum);
}

// ---------------- K5: x_emb = LN(relu(bias + x*w)), tf32-rounded ------------
// one warp per (b,c) row; 8 warps per block
__global__ void xemb_kernel(const float* __restrict__ x,
                            const float* __restrict__ few,
                            const float* __restrict__ feb,
                            const float* __restrict__ lnew,
                            const float* __restrict__ lneb) {
    int lane = threadIdx.x & 31;
    int wid = threadIdx.x >> 5;
    int row = blockIdx.x * 8 + wid;            // = b*256 + c
    int c = row & 255;
    const float xv = x[row];
    const float* wrow = few + c * N256;
    const float* brow = feb + c * N256;
    float v[8];
    float sum = 0.0f, sq = 0.0f;
#pragma unroll
    for (int i = 0; i < 8; i++) {
        int d = lane + i * 32;
        float t = fmaf(xv, wrow[d], brow[d]);
        t = t > 0.0f ? t : 0.0f;
        v[i] = t;
        sum += t;
        sq = fmaf(t, t, sq);
    }
#pragma unroll
    for (int off = 16; off > 0; off >>= 1) {
        sum += __shfl_xor_sync(0xffffffff, sum, off);
        sq  += __shfl_xor_sync(0xffffffff, sq, off);
    }
    float mu = sum * (1.0f / 256.0f);
    float var = sq * (1.0f / 256.0f) - mu * mu;
    float rstd = rsqrtf(var + EPS);
    float* orow = g_xemb + row * N256;
#pragma unroll
    for (int i = 0; i < 8; i++) {
        int d = lane + i * 32;
        orow[d] = to_tf32((v[i] - mu) * rstd * lnew[d] + lneb[d]);
    }
}

// ---------------- K6: out[b] = mask @ xemb[b], tf32 mma, cp.async pipelined -
// out[0,b,p,d] = (1+ew[p]) * sum_c mask[p,c]*xemb[b,c,d] + mask[b,p]*eb[b]
// Block tile 128x128, K-chunk 16, double-buffered cp.async.
__device__ __forceinline__ void mma_tf32(float c[4],
                                         uint32_t a0, uint32_t a1, uint32_t a2, uint32_t a3,
                                         uint32_t b0, uint32_t b1) {
    asm volatile(
        "mma.sync.aligned.m16n8k8.row.col.f32.tf32.tf32.f32 "
        "{%0,%1,%2,%3}, {%4,%5,%6,%7}, {%8,%9}, {%0,%1,%2,%3};"
        : "+f"(c[0]), "+f"(c[1]), "+f"(c[2]), "+f"(c[3])
        : "r"(a0), "r"(a1), "r"(a2), "r"(a3), "r"(b0), "r"(b1));
}

#define AS_STRIDE 20    // 16 + 4 pad  (conflict-free A-frag LDS)
#define BS_STRIDE 136   // 128 + 8 pad (136 mod 32 = 8 -> banks 8*tig+grp, conflict-free)

__global__ __launch_bounds__(256) void out_gemm_kernel(
    const float* __restrict__ ew,
    const float* __restrict__ eb,
    float* __restrict__ out) {
    __shared__ __align__(16) float As[2][128 * AS_STRIDE];
    __shared__ __align__(16) float Bs[2][16 * BS_STRIDE];

    int b = blockIdx.z;
    int m0 = blockIdx.y * 128;
    int n0 = blockIdx.x * 128;
    const float* A = g_mask;                 // [P=256, C=256]
    const float* B = g_xemb + b * 65536;     // [C=256, D=256]

    int tid = threadIdx.x;
    int lane = tid & 31;
    int warp = tid >> 5;
    int wm = (warp & 1) * 64;
    int wn = (warp >> 1) * 32;
    int grp = lane >> 2;      // 0..7
    int tig = lane & 3;       // 0..3

    // per-thread load coordinates (2 float4 per tile per thread)
    int a_r0 = (tid * 2) >> 3;            // via idx=t*256+tid: r=idx>>2
    // recompute properly below per t

    float acc[4][4][4];
#pragma unroll
    for (int i = 0; i < 4; i++)
#pragma unroll
        for (int j = 0; j < 4; j++)
#pragma unroll
            for (int k = 0; k < 4; k++) acc[i][j][k] = 0.0f;

    // issue loads for chunk kt into buffer buf
    auto load_tiles = [&](int buf, int kt) {
        int k0 = kt * 16;
#pragma unroll
        for (int t = 0; t < 2; t++) {
            int idx = t * 256 + tid;
            // A tile: 128 rows x 16 k = 512 float4; r=idx>>2, kc=(idx&3)*4
            int r = idx >> 2;
            int kc = (idx & 3) << 2;
            cp_async16(As[buf] + r * AS_STRIDE + kc,
                       A + (m0 + r) * 256 + k0 + kc);
            // B tile: 16 k x 128 n = 512 float4; r=idx>>5, nc=(idx&31)*4
            int rb = idx >> 5;
            int nc = (idx & 31) << 2;
            cp_async16(Bs[buf] + rb * BS_STRIDE + nc,
                       B + (k0 + rb) * 256 + n0 + nc);
        }
        cp_commit();
    };

    load_tiles(0, 0);

    for (int kt = 0; kt < 16; kt++) {
        int buf = kt & 1;
        if (kt < 15) {
            load_tiles(buf ^ 1, kt + 1);
            cp_wait<1>();
        } else {
            cp_wait<0>();
        }
        __syncthreads();

        const float* as = As[buf];
        const float* bs = Bs[buf];
#pragma unroll
        for (int ks = 0; ks < 2; ks++) {
            int kk = ks * 8;
            uint32_t afr[4][4];
#pragma unroll
            for (int mi = 0; mi < 4; mi++) {
                int rb = wm + mi * 16 + grp;
                int cb = kk + tig;
                afr[mi][0] = __float_as_uint(as[rb * AS_STRIDE + cb]);
                afr[mi][1] = __float_as_uint(as[(rb + 8) * AS_STRIDE + cb]);
                afr[mi][2] = __float_as_uint(as[rb * AS_STRIDE + cb + 4]);
                afr[mi][3] = __float_as_uint(as[(rb + 8) * AS_STRIDE + cb + 4]);
            }
            uint32_t bfr[4][2];
#pragma unroll
            for (int ni = 0; ni < 4; ni++) {
                int nb = wn + ni * 8 + grp;
                int kb = kk + tig;
                bfr[ni][0] = __float_as_uint(bs[kb * BS_STRIDE + nb]);
                bfr[ni][1] = __float_as_uint(bs[(kb + 4) * BS_STRIDE + nb]);
            }
#pragma unroll
            for (int mi = 0; mi < 4; mi++)
#pragma unroll
                for (int ni = 0; ni < 4; ni++)
                    mma_tf32(acc[mi][ni],
                             afr[mi][0], afr[mi][1], afr[mi][2], afr[mi][3],
                             bfr[ni][0], bfr[ni][1]);
        }
        __syncthreads();
    }

    // epilogue: scale by (1+ew[p]) and add mask[b,p]*eb[b]
    const float* maskb = g_mask + b * 256;  // row b of mask
    float ebb = eb[b];
#pragma unroll
    for (int mi = 0; mi < 4; mi++) {
#pragma unroll
        for (int h = 0; h < 2; h++) {
            int p = m0 + wm + mi * 16 + grp + h * 8;
            float scale = 1.0f + ew[p];
            float addv = maskb[p] * ebb;
            long rowoff = ((long)(b * 256 + p)) * 256;
#pragma unroll
            for (int ni = 0; ni < 4; ni++) {
                int d = n0 + wn + ni * 8 + tig * 2;
                float v0 = acc[mi][ni][h * 2 + 0] * scale + addv;
                float v1 = acc[mi][ni][h * 2 + 1] * scale + addv;
                *(float2*)(out + rowoff + d) = make_float2(v0, v1);
            }
        }
    }
}

// ---------------- launch -----------------------------------------------------
extern "C" void kernel_launch(void* const* d_in, const int* in_sizes, int n_in,
                              void* d_out, int out_size) {
    const float* x    = (const float*)d_in[0];   // [B,C]
    const float* prev = (const float*)d_in[1];   // [P,D]
    const float* few  = (const float*)d_in[2];   // [C,D]
    const float* feb  = (const float*)d_in[3];   // [1,C,D]
    const float* lnew = (const float*)d_in[4];
    const float* lneb = (const float*)d_in[5];
    const float* lncw = (const float*)d_in[6];
    const float* lncb = (const float*)d_in[7];
    const float* lnpw = (const float*)d_in[8];
    const float* lnpb = (const float*)d_in[9];
    const float* diw  = (const float*)d_in[10];  // [D,2D]
    const float* dib  = (const float*)d_in[11];  // [D]
    const float* embc = (const float*)d_in[12];  // [C,D]
    const float* embp = (const float*)d_in[13];  // [P,D]
    const float* ew   = (const float*)d_in[14];  // [P,1]
    const float* ebia = (const float*)d_in[15];  // [P]
    float* out = (float*)d_out;

    build_xpin_kernel<<<256, 256>>>(embp, lnpw, lnpb, prev);
    ln_col_kernel<<<256, 256>>>(embc, lncw, lncb);
    xprompt_kernel<<<dim3(16, 16), dim3(16, 16)>>>(diw, dib, embp);
    logits_kernel<<<dim3(16, 16), dim3(16, 16)>>>();
    softmax_kernel<<<256, 256>>>();
    xemb_kernel<<<8192, 256>>>(x, few, feb, lnew, lneb);
    out_gemm_kernel<<<dim3(2, 2, 256), 256>>>(ew, ebia, out);
}